// round 7
// baseline (speedup 1.0000x reference)
#include <cuda_runtime.h>
#include <cuda_fp16.h>
#include <math.h>
#include <stdint.h>

#define B_SZ 2048
#define KIN  64
#define KOUT 64
#define KH   129

// Scratch (device globals: allocation-free per the rules)
__device__ __align__(256) __half2 g_Xh[(size_t)B_SZ * KH * KIN];   // [b][f][j] ~67 MB
__device__ __align__(256) __half2 g_Yh[(size_t)B_SZ * KH * KOUT];  // [b][f][i] ~67 MB
__device__ __align__(256) __half  g_Bh[(size_t)KH * 16384];        // [f][n][k] ~4.2 MB

// ===========================================================================
// helpers
// ===========================================================================
__device__ __forceinline__ uint32_t smem_to_u32(const void* p) {
    uint32_t a;
    asm("{ .reg .u64 t; cvta.to.shared.u64 t, %1; cvt.u32.u64 %0, t; }" : "=r"(a) : "l"(p));
    return a;
}
__device__ __forceinline__ void cp_async16(uint32_t dst, const void* src) {
    asm volatile("cp.async.cg.shared.global [%0], [%1], 16;" :: "r"(dst), "l"(src));
}
#define CP_COMMIT() asm volatile("cp.async.commit_group;" ::: "memory")
#define CP_WAIT1()  asm volatile("cp.async.wait_group 1;" ::: "memory")

#define LDSM_X4(r0, r1, r2, r3, addr) \
    asm volatile("ldmatrix.sync.aligned.m8n8.x4.shared.b16 {%0,%1,%2,%3}, [%4];" \
        : "=r"(r0), "=r"(r1), "=r"(r2), "=r"(r3) : "r"(addr))

#define HMMA16(d, a, b0v, b1v) \
    asm volatile("mma.sync.aligned.m16n8k16.row.col.f32.f16.f16.f32 " \
        "{%0,%1,%2,%3}, {%4,%5,%6,%7}, {%8,%9}, {%0,%1,%2,%3};" \
        : "+f"((d)[0]), "+f"((d)[1]), "+f"((d)[2]), "+f"((d)[3]) \
        : "r"((a)[0]), "r"((a)[1]), "r"((a)[2]), "r"((a)[3]), "r"(b0v), "r"(b1v))

__device__ __forceinline__ float2 cmul(float2 a, float2 b) {
    return make_float2(a.x * b.x - a.y * b.y, a.x * b.y + a.y * b.x);
}

// ===========================================================================
// Radix-2 DIF FFT machinery (constant twiddles, outputs bit-reversed)
// ===========================================================================
#define FC1 0.9238795325112867f
#define FS1 0.3826834323650898f
#define FC2 0.7071067811865476f
#define BF(i, j, cr, ci) {                                   \
    float ux = a[i].x, uy = a[i].y;                          \
    float vx = a[j].x, vy = a[j].y;                          \
    a[i].x = ux + vx; a[i].y = uy + vy;                      \
    float dx = ux - vx, dy = uy - vy;                        \
    a[j].x = dx * (cr) - dy * (ci);                          \
    a[j].y = dx * (ci) + dy * (cr); }

template<bool INV>
__device__ __forceinline__ void fft16_full(float2* a) {
    const float S = INV ? 1.0f : -1.0f;
    BF(0, 8, 1.0f, 0.0f)      BF(1, 9, FC1, S * FS1)
    BF(2, 10, FC2, S * FC2)   BF(3, 11, FS1, S * FC1)
    BF(4, 12, 0.0f, S)        BF(5, 13, -FS1, S * FC1)
    BF(6, 14, -FC2, S * FC2)  BF(7, 15, -FC1, S * FS1)
    BF(0, 4, 1.0f, 0.0f)   BF(1, 5, FC2, S * FC2)
    BF(2, 6, 0.0f, S)      BF(3, 7, -FC2, S * FC2)
    BF(8, 12, 1.0f, 0.0f)  BF(9, 13, FC2, S * FC2)
    BF(10, 14, 0.0f, S)    BF(11, 15, -FC2, S * FC2)
    BF(0, 2, 1.0f, 0.0f)   BF(1, 3, 0.0f, S)
    BF(4, 6, 1.0f, 0.0f)   BF(5, 7, 0.0f, S)
    BF(8, 10, 1.0f, 0.0f)  BF(9, 11, 0.0f, S)
    BF(12, 14, 1.0f, 0.0f) BF(13, 15, 0.0f, S)
    BF(0, 1, 1.0f, 0.0f)   BF(2, 3, 1.0f, 0.0f)
    BF(4, 5, 1.0f, 0.0f)   BF(6, 7, 1.0f, 0.0f)
    BF(8, 9, 1.0f, 0.0f)   BF(10, 11, 1.0f, 0.0f)
    BF(12, 13, 1.0f, 0.0f) BF(14, 15, 1.0f, 0.0f)
}
template<bool INV>
__device__ __forceinline__ void fft8(float2* a) {
    const float S = INV ? 1.0f : -1.0f;
    BF(0, 4, 1.0f, 0.0f)  BF(1, 5, FC2, S * FC2)
    BF(2, 6, 0.0f, S)     BF(3, 7, -FC2, S * FC2)
    BF(0, 2, 1.0f, 0.0f)  BF(1, 3, 0.0f, S)
    BF(4, 6, 1.0f, 0.0f)  BF(5, 7, 0.0f, S)
    BF(0, 1, 1.0f, 0.0f)  BF(2, 3, 1.0f, 0.0f)
    BF(4, 5, 1.0f, 0.0f)  BF(6, 7, 1.0f, 0.0f)
}
#define REV4_LIST {0, 8, 4, 12, 2, 10, 6, 14, 1, 9, 5, 13, 3, 11, 7, 15}
#define REV3_LIST {0, 4, 2, 6, 1, 5, 3, 7}

// smem layout (bytes) for both FFT kernels: tw @0 (2048), regionA @2048 (36864), sZ @38912 (33280)
#define SM_TW  0
#define SM_RA  2048
#define SM_SZ  38912
#define FFT_SMEM 72192

// ---------------------------------------------------------------------------
// Kernel 1: build B_f[n][k] half (2x-expanded complex conj W)
// ---------------------------------------------------------------------------
__global__ void prep_b(const float* __restrict__ Wr, const float* __restrict__ Wi) {
    int idx = blockIdx.x * blockDim.x + threadIdx.x;
    if (idx >= KH * 16384) return;
    int k = idx & 127;
    int n = (idx >> 7) & 127;
    int f = idx >> 14;
    int j = k >> 1, p = k & 1;
    int i = n >> 1, q = n & 1;
    size_t widx = ((size_t)i * KIN + j) * KH + f;
    float v;
    if (p == 0) v = (q == 0) ? Wr[widx] : -Wi[widx];
    else        v = (q == 0) ? Wi[widx] :  Wr[widx];
    g_Bh[idx] = __float2half_rn(v);
}

// ---------------------------------------------------------------------------
// Kernel 2: forward rFFT via 128-pt complex FFT (z[m]=x[2m]+ix[2m+1]).
// CTA: one b, 32 j-blocks (2 CTAs per b). 8 threads per block in stage A.
// ---------------------------------------------------------------------------
__global__ __launch_bounds__(256) void fft_fwd(const float* __restrict__ x) {
    extern __shared__ char sm[];
    float2* tw = (float2*)(sm + SM_TW);           // W_256^k
    float2* sA = (float2*)(sm + SM_RA);           // [g2][q][m1] pad 9 : 32*144
    float2* sZ = (float2*)(sm + SM_SZ);           // [g2][k] pad 130  : 32*130
    __half2* sXh = (__half2*)(sm + SM_RA);        // overlays sA: [g2][132]

    const int rev4[16] = REV4_LIST;
    const int rev3[8]  = REV3_LIST;
    int tid = threadIdx.x;
    {
        float s, c;
        sincospif(-(float)tid * (1.0f / 128.0f), &s, &c);
        tw[tid] = make_float2(c, s);
    }
    int b  = blockIdx.x >> 1;
    int j0 = (blockIdx.x & 1) << 5;

    // Stage A: thread (g2 = block slot, m1); fft16 over m2 of z[m1+8m2]
    int g2 = tid >> 3;
    int m1 = tid & 7;
    const float2* zp = (const float2*)(x + (size_t)b * 16384 + (size_t)(j0 + g2) * 256);
    float2 a[16];
#pragma unroll
    for (int m2 = 0; m2 < 16; m2++) a[m2] = zp[m1 + 8 * m2];
    __syncthreads(); // tw ready

    fft16_full<false>(a);
#pragma unroll
    for (int q = 0; q < 16; q++) {
        float2 H = a[rev4[q]];
        float2 t2 = tw[(2 * m1 * q) & 255]; // W_128^{m1 q}
        sA[g2 * 144 + q * 9 + m1] = cmul(H, t2);
    }
    __syncthreads();

    // Stage B: fft8 over m1 for each (g2, q); 512 tasks, 2 per thread
#pragma unroll
    for (int r = 0; r < 2; r++) {
        int tau = tid + (r << 8);
        int g2b = tau >> 4;
        int q   = tau & 15;
        float2 c[8];
        {
            float2* a = c;
#pragma unroll
            for (int mm = 0; mm < 8; mm++) a[mm] = sA[g2b * 144 + q * 9 + mm];
            fft8<false>(a);
        }
#pragma unroll
        for (int k1 = 0; k1 < 8; k1++)
            sZ[g2b * 130 + q + (k1 << 4)] = c[rev3[k1]];
    }
    __syncthreads();

    // Unpack: X[k] = E + W^k O ; X[128-k] = conj(E - W^k O)
    for (int idx = tid; idx < 32 * 65; idx += 256) {
        int g2b = idx / 65;
        int kk  = idx - g2b * 65;
        float2 Zk = sZ[g2b * 130 + kk];
        float2 Zm = sZ[g2b * 130 + ((128 - kk) & 127)];
        float2 E = make_float2(0.5f * (Zk.x + Zm.x), 0.5f * (Zk.y - Zm.y));
        float2 O = make_float2(0.5f * (Zk.y + Zm.y), -0.5f * (Zk.x - Zm.x));
        float2 P = cmul(O, tw[kk]);
        sXh[g2b * 132 + kk]        = __floats2half2_rn(E.x + P.x, E.y + P.y);
        sXh[g2b * 132 + 128 - kk]  = __floats2half2_rn(E.x - P.x, P.y - E.y);
    }
    __syncthreads();

    // Coalesced out: g_Xh[b][f][j0+jg]
    for (int e = tid; e < 129 * 32; e += 256) {
        int f  = e >> 5;
        int jg = e & 31;
        g_Xh[((size_t)b * KH + f) * KIN + j0 + jg] = sXh[jg * 132 + f];
    }
}

// ---------------------------------------------------------------------------
// Kernel 3: pipelined persistent fp16 mma.sync GEMM (unchanged from R6)
// ---------------------------------------------------------------------------
#define SMB   0
#define SMA0  (128 * 272)
#define SMA1  (2 * 128 * 272)
#define SMTOT (3 * 128 * 272)

__global__ __launch_bounds__(256, 1) void cgemm_h() {
    extern __shared__ char smem[];
    uint32_t sb = smem_to_u32(smem);
    int f = blockIdx.x;
    int tid = threadIdx.x;

    {
        int r = tid & 127, h = tid >> 7;
        const char* src = (const char*)(g_Bh + (size_t)f * 16384) + r * 256 + h * 128;
        uint32_t dst = sb + SMB + r * 272 + h * 128;
#pragma unroll
        for (int cc = 0; cc < 8; cc++) cp_async16(dst + cc * 16, src + cc * 16);
    }

    auto loadA = [&](int bt, int buf) {
        int r = tid & 127, h = tid >> 7;
        const char* src = (const char*)(g_Xh + ((size_t)(bt * 128 + r) * KH + f) * KIN) + h * 128;
        uint32_t dst = sb + (buf ? SMA1 : SMA0) + r * 272 + h * 128;
#pragma unroll
        for (int cc = 0; cc < 8; cc++) cp_async16(dst + cc * 16, src + cc * 16);
    };

    loadA(0, 0);
    CP_COMMIT();

    int lane = tid & 31, warp = tid >> 5;
    int wm = warp & 3;
    int wn = warp >> 2;

    int arow = wm * 32 + (lane & 15);
    int acol2 = ((lane >> 4) << 3) * 2;
    uint32_t aoff0 = (uint32_t)(arow * 272 + acol2);
    uint32_t aoff1 = (uint32_t)((arow + 16) * 272 + acol2);
    int brow = wn * 64 + (lane & 7) + ((lane >> 4) << 3);
    int bcol2 = (((lane >> 3) & 1) << 3) * 2;
    uint32_t boff0 = (uint32_t)(brow * 272 + bcol2);

    const int l4 = lane >> 2, lm = lane & 3;

    for (int it = 0; it < 16; it++) {
        if (it + 1 < 16) loadA(it + 1, (it + 1) & 1);
        CP_COMMIT();
        CP_WAIT1();
        __syncthreads();

        uint32_t abase = sb + ((it & 1) ? SMA1 : SMA0);
        uint32_t bbase = sb + SMB;

        float acc[2][8][4];
#pragma unroll
        for (int mt = 0; mt < 2; mt++)
#pragma unroll
            for (int nt = 0; nt < 8; nt++)
#pragma unroll
                for (int r = 0; r < 4; r++) acc[mt][nt][r] = 0.f;

#pragma unroll
        for (int s = 0; s < 8; s++) {
            uint32_t kb = (uint32_t)s * 32;
            uint32_t a0[4], a1[4];
            LDSM_X4(a0[0], a0[1], a0[2], a0[3], abase + aoff0 + kb);
            LDSM_X4(a1[0], a1[1], a1[2], a1[3], abase + aoff1 + kb);
#pragma unroll
            for (int np = 0; np < 4; np++) {
                uint32_t b0, b1, b2, b3;
                LDSM_X4(b0, b1, b2, b3, bbase + boff0 + (uint32_t)np * (16 * 272) + kb);
                HMMA16(acc[0][np * 2],     a0, b0, b1);
                HMMA16(acc[1][np * 2],     a1, b0, b1);
                HMMA16(acc[0][np * 2 + 1], a0, b2, b3);
                HMMA16(acc[1][np * 2 + 1], a1, b2, b3);
            }
        }

        int b0r = it * 128;
#pragma unroll
        for (int mt = 0; mt < 2; mt++) {
            int mrow = wm * 32 + mt * 16 + l4;
            size_t base0 = ((size_t)(b0r + mrow) * KH + f) * KOUT;
            size_t base1 = base0 + (size_t)8 * KH * KOUT;
#pragma unroll
            for (int nt = 0; nt < 8; nt++) {
                int i = wn * 32 + nt * 4 + lm;
                g_Yh[base0 + i] = __floats2half2_rn(acc[mt][nt][0], acc[mt][nt][1]);
                g_Yh[base1 + i] = __floats2half2_rn(acc[mt][nt][2], acc[mt][nt][3]);
            }
        }
        __syncthreads();
    }
}

// ---------------------------------------------------------------------------
// Kernel 4: inverse rFFT via 128-pt complex IFFT; direct contiguous output.
// CTA: one b, 32 i-blocks (2 CTAs per b).
// ---------------------------------------------------------------------------
__global__ __launch_bounds__(256) void fft_inv(float* __restrict__ out) {
    extern __shared__ char sm[];
    float2*  tw = (float2*)(sm + SM_TW);
    __half2* sY = (__half2*)(sm + SM_RA);   // [f][ig] pad 33 : 129*33 (17KB)
    float2*  sG = (float2*)(sm + SM_RA);    // overlays sY after pack: [ig][m1][q] pad 18
    float2*  sZ = (float2*)(sm + SM_SZ);    // [ig][k] pad 130

    const int rev4[16] = REV4_LIST;
    const int rev3[8]  = REV3_LIST;
    int tid = threadIdx.x;
    {
        float s, c;
        sincospif(-(float)tid * (1.0f / 128.0f), &s, &c);
        tw[tid] = make_float2(c, s);
    }
    int b  = blockIdx.x >> 1;
    int i0 = (blockIdx.x & 1) << 5;

    // Phase 0: stage Y (half2, lossless)
    for (int e = tid; e < 129 * 32; e += 256) {
        int f  = e >> 5;
        int ig = e & 31;
        sY[f * 33 + ig] = g_Yh[((size_t)b * KH + f) * KOUT + i0 + ig];
    }
    __syncthreads();

    // Phase 1: pack Z[k] = E + i W^{-k} O ; Z[128-k] = conj(E - i W^{-k} O)
    for (int idx = tid; idx < 32 * 65; idx += 256) {
        int ig = idx / 65;
        int kk = idx - ig * 65;
        float2 Yk = __half22float2(sY[kk * 33 + ig]);
        float2 Ym = __half22float2(sY[(128 - kk) * 33 + ig]);
        float2 E  = make_float2(0.5f * (Yk.x + Ym.x), 0.5f * (Yk.y - Ym.y));
        float2 O2 = make_float2(0.5f * (Yk.x - Ym.x), 0.5f * (Yk.y + Ym.y));
        float2 Wc = tw[kk];                  // W_256^{kk}; conj = W^{-kk}
        float2 Q  = cmul(O2, make_float2(Wc.x, -Wc.y));
        sZ[ig * 130 + kk] = make_float2(E.x - Q.y, E.y + Q.x);
        if (kk) sZ[ig * 130 + 128 - kk] = make_float2(E.x + Q.y, Q.x - E.y);
    }
    __syncthreads();

    // Phase 2: inverse fft8 over k1 for each (ig, q); twiddle W_128^{-m1 q}
#pragma unroll
    for (int r = 0; r < 2; r++) {
        int tau = tid + (r << 8);
        int ig = tau >> 4;
        int q  = tau & 15;
        float2 c[8];
        {
            float2* a = c;
#pragma unroll
            for (int k1 = 0; k1 < 8; k1++) a[k1] = sZ[ig * 130 + q + (k1 << 4)];
            fft8<true>(a);
        }
#pragma unroll
        for (int mm = 0; mm < 8; mm++) {
            float2 G = c[rev3[mm]];
            float2 t2 = tw[(2 * mm * q) & 255]; // conj applied in cmul
            sG[ig * 144 + mm * 18 + q] = cmul(G, make_float2(t2.x, -t2.y));
        }
    }
    __syncthreads();

    // Phase 3: inverse fft16 over q; thread = (ig, m1); direct float2 output
    {
        int ig = tid >> 3;
        int m1 = tid & 7;
        float2 a[16];
#pragma unroll
        for (int q = 0; q < 16; q++) a[q] = sG[ig * 144 + m1 * 18 + q];
        fft16_full<true>(a);

        float2* op = (float2*)(out + (size_t)b * 16384 + (size_t)(i0 + ig) * 256);
#pragma unroll
        for (int m2 = 0; m2 < 16; m2++) {
            float2 v = a[rev4[m2]];
            op[m1 + 8 * m2] = make_float2(v.x * (1.0f / 128.0f), v.y * (1.0f / 128.0f));
        }
    }
}

// ---------------------------------------------------------------------------
extern "C" void kernel_launch(void* const* d_in, const int* in_sizes, int n_in,
                              void* d_out, int out_size) {
    const float* x  = (const float*)d_in[0];
    const float* Wr = (const float*)d_in[1];
    const float* Wi = (const float*)d_in[2];
    float* out = (float*)d_out;

    cudaFuncSetAttribute(cgemm_h, cudaFuncAttributeMaxDynamicSharedMemorySize, SMTOT);
    cudaFuncSetAttribute(fft_fwd, cudaFuncAttributeMaxDynamicSharedMemorySize, FFT_SMEM);
    cudaFuncSetAttribute(fft_inv, cudaFuncAttributeMaxDynamicSharedMemorySize, FFT_SMEM);

    prep_b<<<(KH * 16384 + 255) / 256, 256>>>(Wr, Wi);
    fft_fwd<<<B_SZ * 2, 256, FFT_SMEM>>>(x);
    cgemm_h<<<KH, 256, SMTOT>>>();
    fft_inv<<<B_SZ * 2, 256, FFT_SMEM>>>(out);
}

// round 8
// speedup vs baseline: 1.1002x; 1.1002x over previous
#include <cuda_runtime.h>
#include <cuda_fp16.h>
#include <math.h>
#include <stdint.h>

#define B_SZ 2048
#define KIN  64
#define KOUT 64
#define KH   129

// Scratch (device globals: allocation-free per the rules)
__device__ __align__(256) __half2 g_Xh[(size_t)B_SZ * KH * KIN];   // [b][f][j] ~67 MB
__device__ __align__(256) __half2 g_Yh[(size_t)B_SZ * KH * KOUT];  // [b][f][i] ~67 MB
__device__ __align__(256) __half  g_Bh[(size_t)KH * 16384];        // [f][n][k] ~4.2 MB

// ===========================================================================
// helpers
// ===========================================================================
__device__ __forceinline__ uint32_t smem_to_u32(const void* p) {
    uint32_t a;
    asm("{ .reg .u64 t; cvta.to.shared.u64 t, %1; cvt.u32.u64 %0, t; }" : "=r"(a) : "l"(p));
    return a;
}
__device__ __forceinline__ void cp_async16(uint32_t dst, const void* src) {
    asm volatile("cp.async.cg.shared.global [%0], [%1], 16;" :: "r"(dst), "l"(src));
}
#define CP_COMMIT() asm volatile("cp.async.commit_group;" ::: "memory")
#define CP_WAIT1()  asm volatile("cp.async.wait_group 1;" ::: "memory")

#define LDSM_X4(r0, r1, r2, r3, addr) \
    asm volatile("ldmatrix.sync.aligned.m8n8.x4.shared.b16 {%0,%1,%2,%3}, [%4];" \
        : "=r"(r0), "=r"(r1), "=r"(r2), "=r"(r3) : "r"(addr))

#define HMMA16(d, a, b0v, b1v) \
    asm volatile("mma.sync.aligned.m16n8k16.row.col.f32.f16.f16.f32 " \
        "{%0,%1,%2,%3}, {%4,%5,%6,%7}, {%8,%9}, {%0,%1,%2,%3};" \
        : "+f"((d)[0]), "+f"((d)[1]), "+f"((d)[2]), "+f"((d)[3]) \
        : "r"((a)[0]), "r"((a)[1]), "r"((a)[2]), "r"((a)[3]), "r"(b0v), "r"(b1v))

__device__ __forceinline__ float2 cmul(float2 a, float2 b) {
    return make_float2(a.x * b.x - a.y * b.y, a.x * b.y + a.y * b.x);
}

// ===========================================================================
// Radix-2 DIF FFT machinery (constant twiddles, outputs bit-reversed)
// ===========================================================================
#define FC1 0.9238795325112867f
#define FS1 0.3826834323650898f
#define FC2 0.7071067811865476f
#define BF(i, j, cr, ci) {                                   \
    float ux = a[i].x, uy = a[i].y;                          \
    float vx = a[j].x, vy = a[j].y;                          \
    a[i].x = ux + vx; a[i].y = uy + vy;                      \
    float dx = ux - vx, dy = uy - vy;                        \
    a[j].x = dx * (cr) - dy * (ci);                          \
    a[j].y = dx * (ci) + dy * (cr); }

template<bool INV>
__device__ __forceinline__ void fft16_full(float2* a) {
    const float S = INV ? 1.0f : -1.0f;
    BF(0, 8, 1.0f, 0.0f)      BF(1, 9, FC1, S * FS1)
    BF(2, 10, FC2, S * FC2)   BF(3, 11, FS1, S * FC1)
    BF(4, 12, 0.0f, S)        BF(5, 13, -FS1, S * FC1)
    BF(6, 14, -FC2, S * FC2)  BF(7, 15, -FC1, S * FS1)
    BF(0, 4, 1.0f, 0.0f)   BF(1, 5, FC2, S * FC2)
    BF(2, 6, 0.0f, S)      BF(3, 7, -FC2, S * FC2)
    BF(8, 12, 1.0f, 0.0f)  BF(9, 13, FC2, S * FC2)
    BF(10, 14, 0.0f, S)    BF(11, 15, -FC2, S * FC2)
    BF(0, 2, 1.0f, 0.0f)   BF(1, 3, 0.0f, S)
    BF(4, 6, 1.0f, 0.0f)   BF(5, 7, 0.0f, S)
    BF(8, 10, 1.0f, 0.0f)  BF(9, 11, 0.0f, S)
    BF(12, 14, 1.0f, 0.0f) BF(13, 15, 0.0f, S)
    BF(0, 1, 1.0f, 0.0f)   BF(2, 3, 1.0f, 0.0f)
    BF(4, 5, 1.0f, 0.0f)   BF(6, 7, 1.0f, 0.0f)
    BF(8, 9, 1.0f, 0.0f)   BF(10, 11, 1.0f, 0.0f)
    BF(12, 13, 1.0f, 0.0f) BF(14, 15, 1.0f, 0.0f)
}
template<bool INV>
__device__ __forceinline__ void fft8(float2* a) {
    const float S = INV ? 1.0f : -1.0f;
    BF(0, 4, 1.0f, 0.0f)  BF(1, 5, FC2, S * FC2)
    BF(2, 6, 0.0f, S)     BF(3, 7, -FC2, S * FC2)
    BF(0, 2, 1.0f, 0.0f)  BF(1, 3, 0.0f, S)
    BF(4, 6, 1.0f, 0.0f)  BF(5, 7, 0.0f, S)
    BF(0, 1, 1.0f, 0.0f)  BF(2, 3, 1.0f, 0.0f)
    BF(4, 5, 1.0f, 0.0f)  BF(6, 7, 1.0f, 0.0f)
}
#define REV4_LIST {0, 8, 4, 12, 2, 10, 6, 14, 1, 9, 5, 13, 3, 11, 7, 15}
#define REV3_LIST {0, 4, 2, 6, 1, 5, 3, 7}

// FFT smem (bytes). Working set: slot(q,blk,m1) = q*257 + blk*8 + m1 (float2)
#define QP 257
#define F_TW  0
#define F_SA  2048
#define F_SXH 34944           // 2048 + 16*257*8 = 34944
#define I_TW  0
#define I_SY  2048
#define I_SZ  19104           // 2048 + 17056 (129*33 half2 staged Y)
#define FFT_SMEM 52224

// ---------------------------------------------------------------------------
// Kernel 1: build B_f[n][k] half (2x-expanded complex conj W)
// ---------------------------------------------------------------------------
__global__ void prep_b(const float* __restrict__ Wr, const float* __restrict__ Wi) {
    int idx = blockIdx.x * blockDim.x + threadIdx.x;
    if (idx >= KH * 16384) return;
    int k = idx & 127;
    int n = (idx >> 7) & 127;
    int f = idx >> 14;
    int j = k >> 1, p = k & 1;
    int i = n >> 1, q = n & 1;
    size_t widx = ((size_t)i * KIN + j) * KH + f;
    float v;
    if (p == 0) v = (q == 0) ? Wr[widx] : -Wi[widx];
    else        v = (q == 0) ? Wi[widx] :  Wr[widx];
    g_Bh[idx] = __float2half_rn(v);
}

// ---------------------------------------------------------------------------
// Kernel 2: forward rFFT via 128-pt complex FFT (z[m]=x[2m]+ix[2m+1]).
// CTA: one b, 32 j-blocks. Conflict-free slot layout, in-place fft8.
// ---------------------------------------------------------------------------
__global__ __launch_bounds__(256) void fft_fwd(const float* __restrict__ x) {
    extern __shared__ char sm[];
    float2*  tw  = (float2*)(sm + F_TW);
    float2*  sA  = (float2*)(sm + F_SA);
    __half2* sXh = (__half2*)(sm + F_SXH);   // [blk][132]

    const int rev4[16] = REV4_LIST;
    const int rev3[8]  = REV3_LIST;
    int tid = threadIdx.x;
    {
        float s, c;
        sincospif(-(float)tid * (1.0f / 128.0f), &s, &c);
        tw[tid] = make_float2(c, s);
    }
    int b  = blockIdx.x >> 1;
    int j0 = (blockIdx.x & 1) << 5;

    // Stage A: thread (g2 = block, m1 in 0..7); fft16 over m2 of z[m1+8m2]
    int g2 = tid >> 3;
    int m1 = tid & 7;
    const float2* zp = (const float2*)(x + (size_t)b * 16384 + (size_t)(j0 + g2) * 256);
    float2 a[16];
#pragma unroll
    for (int m2 = 0; m2 < 16; m2++) a[m2] = zp[m1 + 8 * m2];
    __syncthreads(); // tw ready

    fft16_full<false>(a);
#pragma unroll
    for (int q = 0; q < 16; q++) {
        float2 t2 = tw[(2 * m1 * q) & 255]; // W_128^{m1 q}
        sA[q * QP + g2 * 8 + m1] = cmul(a[rev4[q]], t2);
    }
    __syncthreads();

    // Stage B: in-place fft8 over m1 for each (blk, q); Z[q+16k1] -> slot k1
#pragma unroll
    for (int r = 0; r < 2; r++) {
        int tau = tid + (r << 8);
        int blk = tau >> 4;
        int q   = tau & 15;
        int base = q * QP + blk * 8;
        float2 c[8];
        {
            float2* a = c;
#pragma unroll
            for (int mm = 0; mm < 8; mm++) a[mm] = sA[base + mm];
            fft8<false>(a);
        }
#pragma unroll
        for (int k1 = 0; k1 < 8; k1++)
            sA[base + k1] = c[rev3[k1]];
    }
    __syncthreads();

    // Unpack: X[k] = E + W^k O ; X[128-k] = conj(E - W^k O)
    for (int idx = tid; idx < 32 * 65; idx += 256) {
        int blk = idx / 65;
        int kk  = idx - blk * 65;
        float2 Zk = sA[(kk & 15) * QP + blk * 8 + (kk >> 4)];
        int km = (128 - kk) & 127;
        float2 Zm = sA[(km & 15) * QP + blk * 8 + (km >> 4)];
        float2 E = make_float2(0.5f * (Zk.x + Zm.x), 0.5f * (Zk.y - Zm.y));
        float2 O = make_float2(0.5f * (Zk.y + Zm.y), -0.5f * (Zk.x - Zm.x));
        float2 P = cmul(O, tw[kk]);
        sXh[blk * 132 + kk]       = __floats2half2_rn(E.x + P.x, E.y + P.y);
        sXh[blk * 132 + 128 - kk] = __floats2half2_rn(E.x - P.x, P.y - E.y);
    }
    __syncthreads();

    // Coalesced out: g_Xh[b][f][j0+jg]
    for (int e = tid; e < 129 * 32; e += 256) {
        int f  = e >> 5;
        int jg = e & 31;
        g_Xh[((size_t)b * KH + f) * KIN + j0 + jg] = sXh[jg * 132 + f];
    }
}

// ---------------------------------------------------------------------------
// Kernel 3: pipelined persistent fp16 mma.sync GEMM (unchanged from R6)
// ---------------------------------------------------------------------------
#define SMB   0
#define SMA0  (128 * 272)
#define SMA1  (2 * 128 * 272)
#define SMTOT (3 * 128 * 272)

__global__ __launch_bounds__(256, 1) void cgemm_h() {
    extern __shared__ char smem[];
    uint32_t sb = smem_to_u32(smem);
    int f = blockIdx.x;
    int tid = threadIdx.x;

    {
        int r = tid & 127, h = tid >> 7;
        const char* src = (const char*)(g_Bh + (size_t)f * 16384) + r * 256 + h * 128;
        uint32_t dst = sb + SMB + r * 272 + h * 128;
#pragma unroll
        for (int cc = 0; cc < 8; cc++) cp_async16(dst + cc * 16, src + cc * 16);
    }

    auto loadA = [&](int bt, int buf) {
        int r = tid & 127, h = tid >> 7;
        const char* src = (const char*)(g_Xh + ((size_t)(bt * 128 + r) * KH + f) * KIN) + h * 128;
        uint32_t dst = sb + (buf ? SMA1 : SMA0) + r * 272 + h * 128;
#pragma unroll
        for (int cc = 0; cc < 8; cc++) cp_async16(dst + cc * 16, src + cc * 16);
    };

    loadA(0, 0);
    CP_COMMIT();

    int lane = tid & 31, warp = tid >> 5;
    int wm = warp & 3;
    int wn = warp >> 2;

    int arow = wm * 32 + (lane & 15);
    int acol2 = ((lane >> 4) << 3) * 2;
    uint32_t aoff0 = (uint32_t)(arow * 272 + acol2);
    uint32_t aoff1 = (uint32_t)((arow + 16) * 272 + acol2);
    int brow = wn * 64 + (lane & 7) + ((lane >> 4) << 3);
    int bcol2 = (((lane >> 3) & 1) << 3) * 2;
    uint32_t boff0 = (uint32_t)(brow * 272 + bcol2);

    const int l4 = lane >> 2, lm = lane & 3;

    for (int it = 0; it < 16; it++) {
        if (it + 1 < 16) loadA(it + 1, (it + 1) & 1);
        CP_COMMIT();
        CP_WAIT1();
        __syncthreads();

        uint32_t abase = sb + ((it & 1) ? SMA1 : SMA0);
        uint32_t bbase = sb + SMB;

        float acc[2][8][4];
#pragma unroll
        for (int mt = 0; mt < 2; mt++)
#pragma unroll
            for (int nt = 0; nt < 8; nt++)
#pragma unroll
                for (int r = 0; r < 4; r++) acc[mt][nt][r] = 0.f;

#pragma unroll
        for (int s = 0; s < 8; s++) {
            uint32_t kb = (uint32_t)s * 32;
            uint32_t a0[4], a1[4];
            LDSM_X4(a0[0], a0[1], a0[2], a0[3], abase + aoff0 + kb);
            LDSM_X4(a1[0], a1[1], a1[2], a1[3], abase + aoff1 + kb);
#pragma unroll
            for (int np = 0; np < 4; np++) {
                uint32_t b0, b1, b2, b3;
                LDSM_X4(b0, b1, b2, b3, bbase + boff0 + (uint32_t)np * (16 * 272) + kb);
                HMMA16(acc[0][np * 2],     a0, b0, b1);
                HMMA16(acc[1][np * 2],     a1, b0, b1);
                HMMA16(acc[0][np * 2 + 1], a0, b2, b3);
                HMMA16(acc[1][np * 2 + 1], a1, b2, b3);
            }
        }

        int b0r = it * 128;
#pragma unroll
        for (int mt = 0; mt < 2; mt++) {
            int mrow = wm * 32 + mt * 16 + l4;
            size_t base0 = ((size_t)(b0r + mrow) * KH + f) * KOUT;
            size_t base1 = base0 + (size_t)8 * KH * KOUT;
#pragma unroll
            for (int nt = 0; nt < 8; nt++) {
                int i = wn * 32 + nt * 4 + lm;
                g_Yh[base0 + i] = __floats2half2_rn(acc[mt][nt][0], acc[mt][nt][1]);
                g_Yh[base1 + i] = __floats2half2_rn(acc[mt][nt][2], acc[mt][nt][3]);
            }
        }
        __syncthreads();
    }
}

// ---------------------------------------------------------------------------
// Kernel 4: inverse rFFT via 128-pt complex IFFT; direct contiguous output.
// CTA: one b, 32 i-blocks. Conflict-free slots, in-place fft8.
// ---------------------------------------------------------------------------
__global__ __launch_bounds__(256) void fft_inv(float* __restrict__ out) {
    extern __shared__ char sm[];
    float2*  tw = (float2*)(sm + I_TW);
    __half2* sY = (__half2*)(sm + I_SY);    // [f][ig] pitch 33
    float2*  sZ = (float2*)(sm + I_SZ);     // slot(q, ig, k1) = q*QP + ig*8 + k1

    const int rev4[16] = REV4_LIST;
    const int rev3[8]  = REV3_LIST;
    int tid = threadIdx.x;
    {
        float s, c;
        sincospif(-(float)tid * (1.0f / 128.0f), &s, &c);
        tw[tid] = make_float2(c, s);
    }
    int b  = blockIdx.x >> 1;
    int i0 = (blockIdx.x & 1) << 5;

    // Phase 0: stage Y (half2, lossless)
    for (int e = tid; e < 129 * 32; e += 256) {
        int f  = e >> 5;
        int ig = e & 31;
        sY[f * 33 + ig] = g_Yh[((size_t)b * KH + f) * KOUT + i0 + ig];
    }
    __syncthreads();

    // Phase 1: pack Z[k] = E + i W^{-k} O ; Z[128-k] = conj(E - i W^{-k} O)
    for (int idx = tid; idx < 32 * 65; idx += 256) {
        int ig = idx / 65;
        int kk = idx - ig * 65;
        float2 Yk = __half22float2(sY[kk * 33 + ig]);
        float2 Ym = __half22float2(sY[(128 - kk) * 33 + ig]);
        float2 E  = make_float2(0.5f * (Yk.x + Ym.x), 0.5f * (Yk.y - Ym.y));
        float2 O2 = make_float2(0.5f * (Yk.x - Ym.x), 0.5f * (Yk.y + Ym.y));
        float2 Wc = tw[kk];
        float2 Q  = cmul(O2, make_float2(Wc.x, -Wc.y));
        sZ[(kk & 15) * QP + ig * 8 + (kk >> 4)] = make_float2(E.x - Q.y, E.y + Q.x);
        if (kk) {
            int k2 = 128 - kk;
            sZ[(k2 & 15) * QP + ig * 8 + (k2 >> 4)] = make_float2(E.x + Q.y, Q.x - E.y);
        }
    }
    __syncthreads();

    // Phase 2: in-place inverse fft8 over k1 + twiddle W_128^{-m1 q}
#pragma unroll
    for (int r = 0; r < 2; r++) {
        int tau = tid + (r << 8);
        int ig = tau >> 4;
        int q  = tau & 15;
        int base = q * QP + ig * 8;
        float2 c[8];
        {
            float2* a = c;
#pragma unroll
            for (int k1 = 0; k1 < 8; k1++) a[k1] = sZ[base + k1];
            fft8<true>(a);
        }
#pragma unroll
        for (int mm = 0; mm < 8; mm++) {
            float2 t2 = tw[(2 * mm * q) & 255];
            sZ[base + mm] = cmul(c[rev3[mm]], make_float2(t2.x, -t2.y));
        }
    }
    __syncthreads();

    // Phase 3: inverse fft16 over q; thread = (ig, m1); direct float2 output
    {
        int ig = tid >> 3;
        int m1 = tid & 7;
        float2 a[16];
#pragma unroll
        for (int q = 0; q < 16; q++) a[q] = sZ[q * QP + ig * 8 + m1];
        fft16_full<true>(a);

        float2* op = (float2*)(out + (size_t)b * 16384 + (size_t)(i0 + ig) * 256);
#pragma unroll
        for (int m2 = 0; m2 < 16; m2++) {
            float2 v = a[rev4[m2]];
            op[m1 + 8 * m2] = make_float2(v.x * (1.0f / 128.0f), v.y * (1.0f / 128.0f));
        }
    }
}

// ---------------------------------------------------------------------------
extern "C" void kernel_launch(void* const* d_in, const int* in_sizes, int n_in,
                              void* d_out, int out_size) {
    const float* x  = (const float*)d_in[0];
    const float* Wr = (const float*)d_in[1];
    const float* Wi = (const float*)d_in[2];
    float* out = (float*)d_out;

    cudaFuncSetAttribute(cgemm_h, cudaFuncAttributeMaxDynamicSharedMemorySize, SMTOT);
    cudaFuncSetAttribute(fft_fwd, cudaFuncAttributeMaxDynamicSharedMemorySize, FFT_SMEM);
    cudaFuncSetAttribute(fft_inv, cudaFuncAttributeMaxDynamicSharedMemorySize, FFT_SMEM);

    prep_b<<<(KH * 16384 + 255) / 256, 256>>>(Wr, Wi);
    fft_fwd<<<B_SZ * 2, 256, FFT_SMEM>>>(x);
    cgemm_h<<<KH, 256, SMTOT>>>();
    fft_inv<<<B_SZ * 2, 256, FFT_SMEM>>>(out);
}

// round 9
// speedup vs baseline: 1.4033x; 1.2755x over previous
#include <cuda_runtime.h>
#include <cuda_fp16.h>
#include <math.h>
#include <stdint.h>

#define B_SZ 2048
#define KIN  64
#define KOUT 64
#define KH   129

// Scratch (device globals: allocation-free per the rules)
__device__ __align__(256) __half2 g_Xh[(size_t)B_SZ * KH * KIN];   // [b][f][j] ~67 MB
__device__ __align__(256) __half2 g_Yh[(size_t)B_SZ * KH * KOUT];  // [b][f][i] ~67 MB
__device__ __align__(256) __half  g_Bh[(size_t)KH * 16384];        // [f][n][k] ~4.2 MB

// ===========================================================================
// helpers
// ===========================================================================
__device__ __forceinline__ uint32_t smem_to_u32(const void* p) {
    uint32_t a;
    asm("{ .reg .u64 t; cvta.to.shared.u64 t, %1; cvt.u32.u64 %0, t; }" : "=r"(a) : "l"(p));
    return a;
}
__device__ __forceinline__ void cp_async16(uint32_t dst, const void* src) {
    asm volatile("cp.async.cg.shared.global [%0], [%1], 16;" :: "r"(dst), "l"(src));
}
#define CP_COMMIT() asm volatile("cp.async.commit_group;" ::: "memory")
#define CP_WAIT1()  asm volatile("cp.async.wait_group 1;" ::: "memory")

#define LDSM_X4(r0, r1, r2, r3, addr) \
    asm volatile("ldmatrix.sync.aligned.m8n8.x4.shared.b16 {%0,%1,%2,%3}, [%4];" \
        : "=r"(r0), "=r"(r1), "=r"(r2), "=r"(r3) : "r"(addr))

#define HMMA16(d, a, b0v, b1v) \
    asm volatile("mma.sync.aligned.m16n8k16.row.col.f32.f16.f16.f32 " \
        "{%0,%1,%2,%3}, {%4,%5,%6,%7}, {%8,%9}, {%0,%1,%2,%3};" \
        : "+f"((d)[0]), "+f"((d)[1]), "+f"((d)[2]), "+f"((d)[3]) \
        : "r"((a)[0]), "r"((a)[1]), "r"((a)[2]), "r"((a)[3]), "r"(b0v), "r"(b1v))

__device__ __forceinline__ float2 cmul(float2 a, float2 b) {
    return make_float2(a.x * b.x - a.y * b.y, a.x * b.y + a.y * b.x);
}

// ===========================================================================
// Radix-2 DIF FFT machinery (constant twiddles, outputs bit-reversed)
// ===========================================================================
#define FC1 0.9238795325112867f
#define FS1 0.3826834323650898f
#define FC2 0.7071067811865476f
#define BF(i, j, cr, ci) {                                   \
    float ux = a[i].x, uy = a[i].y;                          \
    float vx = a[j].x, vy = a[j].y;                          \
    a[i].x = ux + vx; a[i].y = uy + vy;                      \
    float dx = ux - vx, dy = uy - vy;                        \
    a[j].x = dx * (cr) - dy * (ci);                          \
    a[j].y = dx * (ci) + dy * (cr); }

template<bool INV>
__device__ __forceinline__ void fft16_full(float2* a) {
    const float S = INV ? 1.0f : -1.0f;
    BF(0, 8, 1.0f, 0.0f)      BF(1, 9, FC1, S * FS1)
    BF(2, 10, FC2, S * FC2)   BF(3, 11, FS1, S * FC1)
    BF(4, 12, 0.0f, S)        BF(5, 13, -FS1, S * FC1)
    BF(6, 14, -FC2, S * FC2)  BF(7, 15, -FC1, S * FS1)
    BF(0, 4, 1.0f, 0.0f)   BF(1, 5, FC2, S * FC2)
    BF(2, 6, 0.0f, S)      BF(3, 7, -FC2, S * FC2)
    BF(8, 12, 1.0f, 0.0f)  BF(9, 13, FC2, S * FC2)
    BF(10, 14, 0.0f, S)    BF(11, 15, -FC2, S * FC2)
    BF(0, 2, 1.0f, 0.0f)   BF(1, 3, 0.0f, S)
    BF(4, 6, 1.0f, 0.0f)   BF(5, 7, 0.0f, S)
    BF(8, 10, 1.0f, 0.0f)  BF(9, 11, 0.0f, S)
    BF(12, 14, 1.0f, 0.0f) BF(13, 15, 0.0f, S)
    BF(0, 1, 1.0f, 0.0f)   BF(2, 3, 1.0f, 0.0f)
    BF(4, 5, 1.0f, 0.0f)   BF(6, 7, 1.0f, 0.0f)
    BF(8, 9, 1.0f, 0.0f)   BF(10, 11, 1.0f, 0.0f)
    BF(12, 13, 1.0f, 0.0f) BF(14, 15, 1.0f, 0.0f)
}
template<bool INV>
__device__ __forceinline__ void fft8(float2* a) {
    const float S = INV ? 1.0f : -1.0f;
    BF(0, 4, 1.0f, 0.0f)  BF(1, 5, FC2, S * FC2)
    BF(2, 6, 0.0f, S)     BF(3, 7, -FC2, S * FC2)
    BF(0, 2, 1.0f, 0.0f)  BF(1, 3, 0.0f, S)
    BF(4, 6, 1.0f, 0.0f)  BF(5, 7, 0.0f, S)
    BF(0, 1, 1.0f, 0.0f)  BF(2, 3, 1.0f, 0.0f)
    BF(4, 5, 1.0f, 0.0f)  BF(6, 7, 1.0f, 0.0f)
}
#define REV4_LIST {0, 8, 4, 12, 2, 10, 6, 14, 1, 9, 5, 13, 3, 11, 7, 15}
#define REV3_LIST {0, 4, 2, 6, 1, 5, 3, 7}

// Slot layout for the 128-pt working set, bank-swizzled:
//   slot(q, blk, m1) = q*257 + blk*8 + (m1 ^ (blk & 7))   (float2 units)
// - fft8 per-thread group of 8: permuted within group, conflict-optimal
// - lane=blk @ fixed (q,m1): 8(blk&1) + (m1^(blk&7)) -> 16 distinct 8B banks
#define QP 257
#define SLOT(q, blk, m1) ((q) * QP + ((blk) << 3) + ((m1) ^ ((blk) & 7)))
#define FFT_SMEM (2048 + 16 * QP * 8)   // 34944 B

// ---------------------------------------------------------------------------
// Kernel 1: build B_f[n][k] half (2x-expanded complex conj W)
// ---------------------------------------------------------------------------
__global__ void prep_b(const float* __restrict__ Wr, const float* __restrict__ Wi) {
    int idx = blockIdx.x * blockDim.x + threadIdx.x;
    if (idx >= KH * 16384) return;
    int k = idx & 127;
    int n = (idx >> 7) & 127;
    int f = idx >> 14;
    int j = k >> 1, p = k & 1;
    int i = n >> 1, q = n & 1;
    size_t widx = ((size_t)i * KIN + j) * KH + f;
    float v;
    if (p == 0) v = (q == 0) ? Wr[widx] : -Wi[widx];
    else        v = (q == 0) ? Wi[widx] :  Wr[widx];
    g_Bh[idx] = __float2half_rn(v);
}

// ---------------------------------------------------------------------------
// Kernel 2: forward rFFT via 128-pt complex FFT (z[m]=x[2m]+ix[2m+1]).
// CTA: one b, 32 j-blocks. Unpack writes g_Xh directly (no staging).
// ---------------------------------------------------------------------------
__global__ __launch_bounds__(256) void fft_fwd(const float* __restrict__ x) {
    extern __shared__ char sm[];
    float2* tw = (float2*)(sm);
    float2* sA = (float2*)(sm + 2048);

    const int rev4[16] = REV4_LIST;
    const int rev3[8]  = REV3_LIST;
    int tid = threadIdx.x;
    {
        float s, c;
        sincospif(-(float)tid * (1.0f / 128.0f), &s, &c);
        tw[tid] = make_float2(c, s);
    }
    int b  = blockIdx.x >> 1;
    int j0 = (blockIdx.x & 1) << 5;

    // Stage A: thread (g2 = block, m1); fft16 over m2 of z[m1+8m2]
    int g2 = tid >> 3;
    int m1 = tid & 7;
    const float2* zp = (const float2*)(x + (size_t)b * 16384 + (size_t)(j0 + g2) * 256);
    float2 a[16];
#pragma unroll
    for (int m2 = 0; m2 < 16; m2++) a[m2] = zp[m1 + 8 * m2];
    __syncthreads(); // tw ready

    fft16_full<false>(a);
#pragma unroll
    for (int q = 0; q < 16; q++) {
        float2 t2 = tw[(2 * m1 * q) & 255]; // W_128^{m1 q}
        sA[SLOT(q, g2, m1)] = cmul(a[rev4[q]], t2);
    }
    __syncthreads();

    // Stage B: in-place fft8 over m1 for each (blk, q); Z[q+16k1] -> slot k1
#pragma unroll
    for (int r = 0; r < 2; r++) {
        int tau = tid + (r << 8);
        int blk = tau >> 4;
        int q   = tau & 15;
        float2 c[8];
        {
            float2* a = c;
#pragma unroll
            for (int mm = 0; mm < 8; mm++) a[mm] = sA[SLOT(q, blk, mm)];
            fft8<false>(a);
        }
#pragma unroll
        for (int k1 = 0; k1 < 8; k1++)
            sA[SLOT(q, blk, k1)] = c[rev3[k1]];
    }
    __syncthreads();

    // Unpack + direct coalesced gmem write (lane = blk):
    // X[k] = E + W^k O ; X[128-k] = conj(E - W^k O)
    for (int idx = tid; idx < 65 * 32; idx += 256) {
        int blk = idx & 31;
        int kk  = idx >> 5;
        float2 Zk = sA[SLOT(kk & 15, blk, kk >> 4)];
        int km = (128 - kk) & 127;
        float2 Zm = sA[SLOT(km & 15, blk, km >> 4)];
        float2 E = make_float2(0.5f * (Zk.x + Zm.x), 0.5f * (Zk.y - Zm.y));
        float2 O = make_float2(0.5f * (Zk.y + Zm.y), -0.5f * (Zk.x - Zm.x));
        float2 P = cmul(O, tw[kk]);
        g_Xh[((size_t)b * KH + kk) * KIN + j0 + blk] =
            __floats2half2_rn(E.x + P.x, E.y + P.y);
        g_Xh[((size_t)b * KH + (128 - kk)) * KIN + j0 + blk] =
            __floats2half2_rn(E.x - P.x, P.y - E.y);
    }
}

// ---------------------------------------------------------------------------
// Kernel 3: pipelined persistent fp16 mma.sync GEMM (unchanged)
// ---------------------------------------------------------------------------
#define SMB   0
#define SMA0  (128 * 272)
#define SMA1  (2 * 128 * 272)
#define SMTOT (3 * 128 * 272)

__global__ __launch_bounds__(256, 1) void cgemm_h() {
    extern __shared__ char smem[];
    uint32_t sb = smem_to_u32(smem);
    int f = blockIdx.x;
    int tid = threadIdx.x;

    {
        int r = tid & 127, h = tid >> 7;
        const char* src = (const char*)(g_Bh + (size_t)f * 16384) + r * 256 + h * 128;
        uint32_t dst = sb + SMB + r * 272 + h * 128;
#pragma unroll
        for (int cc = 0; cc < 8; cc++) cp_async16(dst + cc * 16, src + cc * 16);
    }

    auto loadA = [&](int bt, int buf) {
        int r = tid & 127, h = tid >> 7;
        const char* src = (const char*)(g_Xh + ((size_t)(bt * 128 + r) * KH + f) * KIN) + h * 128;
        uint32_t dst = sb + (buf ? SMA1 : SMA0) + r * 272 + h * 128;
#pragma unroll
        for (int cc = 0; cc < 8; cc++) cp_async16(dst + cc * 16, src + cc * 16);
    };

    loadA(0, 0);
    CP_COMMIT();

    int lane = tid & 31, warp = tid >> 5;
    int wm = warp & 3;
    int wn = warp >> 2;

    int arow = wm * 32 + (lane & 15);
    int acol2 = ((lane >> 4) << 3) * 2;
    uint32_t aoff0 = (uint32_t)(arow * 272 + acol2);
    uint32_t aoff1 = (uint32_t)((arow + 16) * 272 + acol2);
    int brow = wn * 64 + (lane & 7) + ((lane >> 4) << 3);
    int bcol2 = (((lane >> 3) & 1) << 3) * 2;
    uint32_t boff0 = (uint32_t)(brow * 272 + bcol2);

    const int l4 = lane >> 2, lm = lane & 3;

    for (int it = 0; it < 16; it++) {
        if (it + 1 < 16) loadA(it + 1, (it + 1) & 1);
        CP_COMMIT();
        CP_WAIT1();
        __syncthreads();

        uint32_t abase = sb + ((it & 1) ? SMA1 : SMA0);
        uint32_t bbase = sb + SMB;

        float acc[2][8][4];
#pragma unroll
        for (int mt = 0; mt < 2; mt++)
#pragma unroll
            for (int nt = 0; nt < 8; nt++)
#pragma unroll
                for (int r = 0; r < 4; r++) acc[mt][nt][r] = 0.f;

#pragma unroll
        for (int s = 0; s < 8; s++) {
            uint32_t kb = (uint32_t)s * 32;
            uint32_t a0[4], a1[4];
            LDSM_X4(a0[0], a0[1], a0[2], a0[3], abase + aoff0 + kb);
            LDSM_X4(a1[0], a1[1], a1[2], a1[3], abase + aoff1 + kb);
#pragma unroll
            for (int np = 0; np < 4; np++) {
                uint32_t b0, b1, b2, b3;
                LDSM_X4(b0, b1, b2, b3, bbase + boff0 + (uint32_t)np * (16 * 272) + kb);
                HMMA16(acc[0][np * 2],     a0, b0, b1);
                HMMA16(acc[1][np * 2],     a1, b0, b1);
                HMMA16(acc[0][np * 2 + 1], a0, b2, b3);
                HMMA16(acc[1][np * 2 + 1], a1, b2, b3);
            }
        }

        int b0r = it * 128;
#pragma unroll
        for (int mt = 0; mt < 2; mt++) {
            int mrow = wm * 32 + mt * 16 + l4;
            size_t base0 = ((size_t)(b0r + mrow) * KH + f) * KOUT;
            size_t base1 = base0 + (size_t)8 * KH * KOUT;
#pragma unroll
            for (int nt = 0; nt < 8; nt++) {
                int i = wn * 32 + nt * 4 + lm;
                g_Yh[base0 + i] = __floats2half2_rn(acc[mt][nt][0], acc[mt][nt][1]);
                g_Yh[base1 + i] = __floats2half2_rn(acc[mt][nt][2], acc[mt][nt][3]);
            }
        }
        __syncthreads();
    }
}

// ---------------------------------------------------------------------------
// Kernel 4: inverse rFFT via 128-pt complex IFFT; direct gmem in AND out.
// CTA: one b, 32 i-blocks.
// ---------------------------------------------------------------------------
__global__ __launch_bounds__(256) void fft_inv(float* __restrict__ out) {
    extern __shared__ char sm[];
    float2* tw = (float2*)(sm);
    float2* sZ = (float2*)(sm + 2048);

    const int rev4[16] = REV4_LIST;
    const int rev3[8]  = REV3_LIST;
    int tid = threadIdx.x;
    {
        float s, c;
        sincospif(-(float)tid * (1.0f / 128.0f), &s, &c);
        tw[tid] = make_float2(c, s);
    }
    int b  = blockIdx.x >> 1;
    int i0 = (blockIdx.x & 1) << 5;
    __syncthreads(); // tw ready

    // Phase 1: read Y directly from gmem (lane = ig, coalesced rows) and pack
    // Z[k] = E + i W^{-k} O ; Z[128-k] = conj(E - i W^{-k} O)
    for (int idx = tid; idx < 65 * 32; idx += 256) {
        int ig = idx & 31;
        int kk = idx >> 5;
        float2 Yk = __half22float2(g_Yh[((size_t)b * KH + kk) * KOUT + i0 + ig]);
        float2 Ym = __half22float2(g_Yh[((size_t)b * KH + (128 - kk)) * KOUT + i0 + ig]);
        float2 E  = make_float2(0.5f * (Yk.x + Ym.x), 0.5f * (Yk.y - Ym.y));
        float2 O2 = make_float2(0.5f * (Yk.x - Ym.x), 0.5f * (Yk.y + Ym.y));
        float2 Wc = tw[kk];
        float2 Q  = cmul(O2, make_float2(Wc.x, -Wc.y));
        sZ[SLOT(kk & 15, ig, kk >> 4)] = make_float2(E.x - Q.y, E.y + Q.x);
        if (kk) {
            int k2 = 128 - kk;
            sZ[SLOT(k2 & 15, ig, k2 >> 4)] = make_float2(E.x + Q.y, Q.x - E.y);
        }
    }
    __syncthreads();

    // Phase 2: in-place inverse fft8 over k1 + twiddle W_128^{-m1 q}
#pragma unroll
    for (int r = 0; r < 2; r++) {
        int tau = tid + (r << 8);
        int ig = tau >> 4;
        int q  = tau & 15;
        float2 c[8];
        {
            float2* a = c;
#pragma unroll
            for (int k1 = 0; k1 < 8; k1++) a[k1] = sZ[SLOT(q, ig, k1)];
            fft8<true>(a);
        }
#pragma unroll
        for (int mm = 0; mm < 8; mm++) {
            float2 t2 = tw[(2 * mm * q) & 255];
            sZ[SLOT(q, ig, mm)] = cmul(c[rev3[mm]], make_float2(t2.x, -t2.y));
        }
    }
    __syncthreads();

    // Phase 3: inverse fft16 over q; thread = (ig, m1); direct float2 output
    {
        int ig = tid >> 3;
        int m1 = tid & 7;
        float2 a[16];
#pragma unroll
        for (int q = 0; q < 16; q++) a[q] = sZ[SLOT(q, ig, m1)];
        fft16_full<true>(a);

        float2* op = (float2*)(out + (size_t)b * 16384 + (size_t)(i0 + ig) * 256);
#pragma unroll
        for (int m2 = 0; m2 < 16; m2++) {
            float2 v = a[rev4[m2]];
            op[m1 + 8 * m2] = make_float2(v.x * (1.0f / 128.0f), v.y * (1.0f / 128.0f));
        }
    }
}

// ---------------------------------------------------------------------------
extern "C" void kernel_launch(void* const* d_in, const int* in_sizes, int n_in,
                              void* d_out, int out_size) {
    const float* x  = (const float*)d_in[0];
    const float* Wr = (const float*)d_in[1];
    const float* Wi = (const float*)d_in[2];
    float* out = (float*)d_out;

    cudaFuncSetAttribute(cgemm_h, cudaFuncAttributeMaxDynamicSharedMemorySize, SMTOT);
    cudaFuncSetAttribute(fft_fwd, cudaFuncAttributeMaxDynamicSharedMemorySize, FFT_SMEM);
    cudaFuncSetAttribute(fft_inv, cudaFuncAttributeMaxDynamicSharedMemorySize, FFT_SMEM);

    prep_b<<<(KH * 16384 + 255) / 256, 256>>>(Wr, Wi);
    fft_fwd<<<B_SZ * 2, 256, FFT_SMEM>>>(x);
    cgemm_h<<<KH, 256, SMTOT>>>();
    fft_inv<<<B_SZ * 2, 256, FFT_SMEM>>>(out);
}